// round 14
// baseline (speedup 1.0000x reference)
#include <cuda_runtime.h>
#include <cuda_bf16.h>

#define NGROUPS 4
#define COUNT   96
#define BATCH   8
#define IMG     224
#define NPIX    (IMG * IMG)
#define ACC_N   (NGROUPS * BATCH * COUNT)
#define KSMAX   16
#define NCH     32      // pixels per CTA chunk (4 n-tiles of 8)
#define LW      40      // staged raw row width (NCH + K - 1 <= 40)

typedef unsigned int u32;

__device__ float g_cnt[ACC_N];
__device__ float g_sum[ACC_N];
__device__ int   g_max[ACC_N];
// A fragments prepacked in m16n8k16 register layout: [g][term][mtile][ks][lane][4] u32
__device__ u32 g_afrag[NGROUPS * 2 * 6 * KSMAX * 128];

__global__ void zero_acc_kernel() {
    int i = blockIdx.x * blockDim.x + threadIdx.x;
    if (i < ACC_N) { g_cnt[i] = 0.0f; g_sum[i] = 0.0f; g_max[i] = 0; }
}

__device__ __forceinline__ unsigned short bf16_bits(float v) {
    __nv_bfloat16 b = __float2bfloat16(v);
    return __bfloat16_as_ushort(b);
}

__global__ void prepack_afrag_kernel(const float* __restrict__ w3, const float* __restrict__ w5,
                                     const float* __restrict__ w7, const float* __restrict__ w9)
{
    int i = blockIdx.x * blockDim.x + threadIdx.x;
    const int TOT = NGROUPS * 2 * 6 * KSMAX * 128;
    if (i >= TOT) return;
    int r  = i & 3;
    int l  = (i >> 2) & 31;
    int ks = (i >> 7) & 15;
    int hi = i >> 11;              // [g][t][mt]
    int mt = hi % 6;
    int t  = (hi / 6) % 2;
    int g  = hi / 12;
    const int kss[4] = {3, 5, 7, 9};
    int K = kss[g], KK = K * K, K3 = 3 * KK;
    const float* W = (g == 0) ? w3 : (g == 1) ? w5 : (g == 2) ? w7 : w9;

    int row = (l >> 2) + (r & 1) * 8;
    int oc  = mt * 16 + row;
    int kb  = ks * 16 + (l & 3) * 2 + ((r >> 1) & 1) * 8;

    unsigned short us[2];
    #pragma unroll
    for (int e = 0; e < 2; ++e) {
        int k = kb + e;
        float v = 0.0f;
        if (k < K3) {
            int ci = k / KK, rem = k - ci * KK;
            int dy = rem / K, dx = rem - dy * K;
            v = W[((oc * 3 + ci) * K + dy) * K + dx];
        }
        float h = __bfloat162float(__float2bfloat16(v));
        us[e] = (t == 0) ? bf16_bits(v) : bf16_bits(v - h);
    }
    g_afrag[i] = (u32)us[0] | ((u32)us[1] << 16);
}

__device__ __forceinline__ u32 smem_u32(const void* p) {
    u32 a;
    asm("{ .reg .u64 t; cvta.to.shared.u64 t, %1; cvt.u32.u64 %0, t; }" : "=r"(a) : "l"(p));
    return a;
}
__device__ __forceinline__ void mma16816(float* c, const u32* a, u32 b0, u32 b1) {
    asm volatile(
        "mma.sync.aligned.m16n8k16.row.col.f32.bf16.bf16.f32 "
        "{%0,%1,%2,%3}, {%4,%5,%6,%7}, {%8,%9}, {%0,%1,%2,%3};"
        : "+f"(c[0]), "+f"(c[1]), "+f"(c[2]), "+f"(c[3])
        : "r"(a[0]), "r"(a[1]), "r"(a[2]), "r"(a[3]), "r"(b0), "r"(b1));
}
// x4 lane-split: lanes 0-15 -> BtH (k-offsets 0/8), lanes 16-31 -> BtL.
// Returns {b0,b1} = hi fragment, {b2,b3} = lo fragment of the same n-tile.
__device__ __forceinline__ void ldsm_x4(u32& b0, u32& b1, u32& b2, u32& b3, u32 addr) {
    asm volatile("ldmatrix.sync.aligned.m8n8.x4.shared.b16 {%0,%1,%2,%3}, [%4];"
                 : "=r"(b0), "=r"(b1), "=r"(b2), "=r"(b3) : "r"(addr));
}

// smem sizing helpers (host+device)
__host__ __device__ constexpr int ks_of(int K)    { return (3 * K * K + 15) / 16; }
__host__ __device__ constexpr int ks16_of(int K)  { return ks_of(K) * 16; }
__host__ __device__ constexpr int kpad_of(int K)  { return ks16_of(K) + 8; }   // odd 16B-stride
__host__ __device__ constexpr int slab_bytes(int K) { return NCH * kpad_of(K) * 2; }
__host__ __device__ constexpr int dyn_bytes(int K)  { return 2 * slab_bytes(K); }

// CTA = (nchunk, y, batch). 192 threads, 6 warps = (3 m-pairs) x (2 n-halves).
// Each warp: 2 m16 oc-tiles x 2 n-tiles -> acc = 16 floats.
template <int K>
__global__ __launch_bounds__(192)
void conv_mma_kernel(const float* __restrict__ X, const float* __restrict__ Bv, int group)
{
    constexpr int P = (K - 1) / 2, KK = K * K, K3 = 3 * KK;
    constexpr int KS = ks_of(K);
    constexpr int KS16 = ks16_of(K);
    constexpr int KPAD = kpad_of(K);

    __shared__ __nv_bfloat16 rawH[3 * K * LW];
    __shared__ __nv_bfloat16 rawL[3 * K * LW];
    __shared__ int s_ofs[KS16];
    extern __shared__ __align__(16) char dynsm[];
    __nv_bfloat16* BtH = (__nv_bfloat16*)dynsm;
    __nv_bfloat16* BtL = (__nv_bfloat16*)(dynsm + slab_bytes(K));

    const int n0   = blockIdx.x * NCH;
    const int y    = blockIdx.y;
    const int b    = blockIdx.z;
    const int tid  = threadIdx.x;
    const int w    = tid >> 5;
    const int lane = tid & 31;
    const int mp   = w >> 1;          // m-pair 0..2 (m-tiles 2mp, 2mp+1)
    const int nh   = w & 1;           // n-half 0..1 (n-tiles 2nh, 2nh+1)

    // ---- k -> raw-offset table ----
    for (int k = tid; k < KS16; k += 192) {
        int o = -1;
        if (k < K3) {
            int ci = k / KK, rem = k - ci * KK;
            int dy = rem / K, dx = rem - dy * K;
            o = (ci * K + dy) * LW + dx;
        }
        s_ofs[k] = o;
    }

    // ---- stage raw rows (bf16 hi/lo), zero outside image ----
    const float* Xb = X + (size_t)b * 3 * NPIX;
    for (int i = tid; i < 3 * K * LW; i += 192) {
        int ci = i / (K * LW);
        int r  = i % (K * LW);
        int dy = r / LW, j = r % LW;
        int iy = y - P + dy, ix = n0 - P + j;
        float v = 0.0f;
        if (iy >= 0 && iy < IMG && ix >= 0 && ix < IMG)
            v = Xb[(ci * IMG + iy) * IMG + ix];
        __nv_bfloat16 h = __float2bfloat16(v);
        rawH[i] = h;
        rawL[i] = __float2bfloat16(v - __bfloat162float(h));
    }
    __syncthreads();

    // ---- build BOTH B slabs in one pass (table-driven) ----
    const __nv_bfloat16 z = __float2bfloat16(0.0f);
    for (int i = tid; i < NCH * KS16; i += 192) {
        int n = i / KS16, k = i - n * KS16;
        int o = s_ofs[k];
        __nv_bfloat16 h = z, l = z;
        if (o >= 0) { h = rawH[o + n]; l = rawL[o + n]; }
        int d = n * KPAD + k;
        BtH[d] = h;
        BtL[d] = l;
    }
    __syncthreads();

    float acc[2][2][4];
    #pragma unroll
    for (int mt = 0; mt < 2; ++mt)
        #pragma unroll
        for (int nt = 0; nt < 2; ++nt)
            #pragma unroll
            for (int c = 0; c < 4; ++c) acc[mt][nt][c] = 0.0f;

    // a-frag pointers for m-tiles 2mp and 2mp+1, hi and lo terms
    const u32* afH0 = &g_afrag[(((group * 2 + 0) * 6 + 2 * mp + 0) * KSMAX) * 128];
    const u32* afH1 = &g_afrag[(((group * 2 + 0) * 6 + 2 * mp + 1) * KSMAX) * 128];
    const u32* afL0 = &g_afrag[(((group * 2 + 1) * 6 + 2 * mp + 0) * KSMAX) * 128];
    const u32* afL1 = &g_afrag[(((group * 2 + 1) * 6 + 2 * mp + 1) * KSMAX) * 128];

    // ldsm.x4 lane-split addressing
    const u32 rowOff = (u32)((((lane & 7) * KPAD) + ((lane >> 3) & 1) * 8) * 2);
    const u32 lmBase = ((lane < 16) ? smem_u32(BtH) : smem_u32(BtL)) + rowOff;

    // ---- mainloop: per ks, 2 x ldsm.x4 + 12 MMAs ----
    #pragma unroll
    for (int ks = 0; ks < KS; ++ks) {
        u32 ah0[4], ah1[4], al0[4], al1[4];
        #pragma unroll
        for (int r = 0; r < 4; ++r) {
            ah0[r] = afH0[ks * 128 + lane * 4 + r];
            ah1[r] = afH1[ks * 128 + lane * 4 + r];
            al0[r] = afL0[ks * 128 + lane * 4 + r];
            al1[r] = afL1[ks * 128 + lane * 4 + r];
        }
        #pragma unroll
        for (int nt = 0; nt < 2; ++nt) {
            const int ntile = 2 * nh + nt;
            u32 b0, b1, c0, c1;
            ldsm_x4(b0, b1, c0, c1, lmBase + (u32)((ntile * 8 * KPAD + ks * 16) * 2));
            mma16816(acc[0][nt], ah0, b0, b1);   // AhBh  (mt0)
            mma16816(acc[1][nt], ah1, b0, b1);   // AhBh  (mt1)
            mma16816(acc[0][nt], al0, b0, b1);   // AlBh  (mt0)
            mma16816(acc[1][nt], al1, b0, b1);   // AlBh  (mt1)
            mma16816(acc[0][nt], ah0, c0, c1);   // AhBl  (mt0)
            mma16816(acc[1][nt], ah1, c0, c1);   // AhBl  (mt1)
        }
    }

    // ---- epilogue: bias+relu+pool per m-tile, quad reduce, atomics ----
    const int r0 = lane >> 2;
    #pragma unroll
    for (int mt = 0; mt < 2; ++mt) {
        const int ocbase = (2 * mp + mt) * 16;
        const float bias0 = Bv[ocbase + r0];
        const float bias1 = Bv[ocbase + r0 + 8];
        float cnt0 = 0, sum0 = 0, mx0 = 0, cnt1 = 0, sum1 = 0, mx1 = 0;
        #pragma unroll
        for (int nt = 0; nt < 2; ++nt) {
            #pragma unroll
            for (int c = 0; c < 2; ++c) {
                float v = acc[mt][nt][c] + bias0;
                float rl = fmaxf(v, 0.0f);
                cnt0 += (v > 0.0f) ? 1.0f : 0.0f; sum0 += rl; mx0 = fmaxf(mx0, rl);
            }
            #pragma unroll
            for (int c = 2; c < 4; ++c) {
                float v = acc[mt][nt][c] + bias1;
                float rl = fmaxf(v, 0.0f);
                cnt1 += (v > 0.0f) ? 1.0f : 0.0f; sum1 += rl; mx1 = fmaxf(mx1, rl);
            }
        }
        #pragma unroll
        for (int m = 1; m <= 2; m <<= 1) {
            cnt0 += __shfl_xor_sync(0xffffffffu, cnt0, m);
            sum0 += __shfl_xor_sync(0xffffffffu, sum0, m);
            mx0   = fmaxf(mx0, __shfl_xor_sync(0xffffffffu, mx0, m));
            cnt1 += __shfl_xor_sync(0xffffffffu, cnt1, m);
            sum1 += __shfl_xor_sync(0xffffffffu, sum1, m);
            mx1   = fmaxf(mx1, __shfl_xor_sync(0xffffffffu, mx1, m));
        }
        if ((lane & 3) == 0) {
            int base = (group * BATCH + b) * COUNT + ocbase;
            int i0 = base + r0, i1 = base + r0 + 8;
            atomicAdd(&g_cnt[i0], cnt0); atomicAdd(&g_sum[i0], sum0);
            atomicMax(&g_max[i0], __float_as_int(mx0));
            atomicAdd(&g_cnt[i1], cnt1); atomicAdd(&g_sum[i1], sum1);
            atomicMax(&g_max[i1], __float_as_int(mx1));
        }
    }
}

__global__ void finalize_kernel(float* __restrict__ out) {
    int i = blockIdx.x * blockDim.x + threadIdx.x;
    if (i >= ACC_N) return;
    int g = i / (BATCH * COUNT);
    int r = i % (BATCH * COUNT);
    int b = r / COUNT;
    int c = r % COUNT;
    float cnt = g_cnt[i];
    float sum = g_sum[i];
    float mx  = __int_as_float(g_max[i]);
    float ppv = cnt * (1.0f / (float)NPIX);
    float mpv = (cnt > 0.0f) ? (sum / cnt) : 0.0f;
    float* o = out + (size_t)b * (NGROUPS * 3 * COUNT) + g * (3 * COUNT);
    o[c]             = ppv;
    o[COUNT + c]     = mpv;
    o[2 * COUNT + c] = mx;
}

extern "C" void kernel_launch(void* const* d_in, const int* in_sizes, int n_in,
                              void* d_out, int out_size)
{
    const float* X  = (const float*)d_in[0];
    const float* w3 = (const float*)d_in[1];
    const float* b3 = (const float*)d_in[2];
    const float* w5 = (const float*)d_in[3];
    const float* b5 = (const float*)d_in[4];
    const float* w7 = (const float*)d_in[5];
    const float* b7 = (const float*)d_in[6];
    const float* w9 = (const float*)d_in[7];
    const float* b9 = (const float*)d_in[8];
    float* out = (float*)d_out;

    cudaFuncSetAttribute(conv_mma_kernel<3>, cudaFuncAttributeMaxDynamicSharedMemorySize, dyn_bytes(3));
    cudaFuncSetAttribute(conv_mma_kernel<5>, cudaFuncAttributeMaxDynamicSharedMemorySize, dyn_bytes(5));
    cudaFuncSetAttribute(conv_mma_kernel<7>, cudaFuncAttributeMaxDynamicSharedMemorySize, dyn_bytes(7));
    cudaFuncSetAttribute(conv_mma_kernel<9>, cudaFuncAttributeMaxDynamicSharedMemorySize, dyn_bytes(9));

    zero_acc_kernel<<<(ACC_N + 255) / 256, 256>>>();
    const int TOT = NGROUPS * 2 * 6 * KSMAX * 128;
    prepack_afrag_kernel<<<(TOT + 255) / 256, 256>>>(w3, w5, w7, w9);

    dim3 grid(IMG / NCH, IMG, BATCH);   // (7 chunks, 224 rows, 8 batches)
    conv_mma_kernel<3><<<grid, 192, dyn_bytes(3)>>>(X, b3, 0);
    conv_mma_kernel<5><<<grid, 192, dyn_bytes(5)>>>(X, b5, 1);
    conv_mma_kernel<7><<<grid, 192, dyn_bytes(7)>>>(X, b7, 2);
    conv_mma_kernel<9><<<grid, 192, dyn_bytes(9)>>>(X, b9, 3);

    finalize_kernel<<<(ACC_N + 255) / 256, 256>>>(out);
}

// round 15
// speedup vs baseline: 1.0918x; 1.0918x over previous
#include <cuda_runtime.h>
#include <cuda_bf16.h>

#define NGROUPS 4
#define COUNT   96
#define BATCH   8
#define IMG     224
#define NPIX    (IMG * IMG)
#define ACC_N   (NGROUPS * BATCH * COUNT)
#define KSMAX   16
#define NCH     56      // pixels per CTA chunk (7 n-tiles of 8)
#define LW      64      // staged raw row width

typedef unsigned int u32;

__device__ float g_cnt[ACC_N];
__device__ float g_sum[ACC_N];
__device__ int   g_max[ACC_N];
// A fragments prepacked in m16n8k16 register layout: [g][term][mtile][ks][lane][4] u32
__device__ u32 g_afrag[NGROUPS * 2 * 6 * KSMAX * 128];

__global__ void zero_acc_kernel() {
    int i = blockIdx.x * blockDim.x + threadIdx.x;
    if (i < ACC_N) { g_cnt[i] = 0.0f; g_sum[i] = 0.0f; g_max[i] = 0; }
}

__device__ __forceinline__ unsigned short bf16_bits(float v) {
    __nv_bfloat16 b = __float2bfloat16(v);
    return __bfloat16_as_ushort(b);
}

__global__ void prepack_afrag_kernel(const float* __restrict__ w3, const float* __restrict__ w5,
                                     const float* __restrict__ w7, const float* __restrict__ w9)
{
    int i = blockIdx.x * blockDim.x + threadIdx.x;
    const int TOT = NGROUPS * 2 * 6 * KSMAX * 128;
    if (i >= TOT) return;
    int r  = i & 3;
    int l  = (i >> 2) & 31;
    int ks = (i >> 7) & 15;
    int hi = i >> 11;              // [g][t][mt]
    int mt = hi % 6;
    int t  = (hi / 6) % 2;
    int g  = hi / 12;
    const int kss[4] = {3, 5, 7, 9};
    int K = kss[g], KK = K * K, K3 = 3 * KK;
    const float* W = (g == 0) ? w3 : (g == 1) ? w5 : (g == 2) ? w7 : w9;

    int row = (l >> 2) + (r & 1) * 8;
    int oc  = mt * 16 + row;
    int kb  = ks * 16 + (l & 3) * 2 + ((r >> 1) & 1) * 8;

    unsigned short us[2];
    #pragma unroll
    for (int e = 0; e < 2; ++e) {
        int k = kb + e;
        float v = 0.0f;
        if (k < K3) {
            int ci = k / KK, rem = k - ci * KK;
            int dy = rem / K, dx = rem - dy * K;
            v = W[((oc * 3 + ci) * K + dy) * K + dx];
        }
        float h = __bfloat162float(__float2bfloat16(v));
        us[e] = (t == 0) ? bf16_bits(v) : bf16_bits(v - h);
    }
    g_afrag[i] = (u32)us[0] | ((u32)us[1] << 16);
}

__device__ __forceinline__ u32 smem_u32(const void* p) {
    u32 a;
    asm("{ .reg .u64 t; cvta.to.shared.u64 t, %1; cvt.u32.u64 %0, t; }" : "=r"(a) : "l"(p));
    return a;
}
__device__ __forceinline__ void mma16816(float* c, const u32* a, u32 b0, u32 b1) {
    asm volatile(
        "mma.sync.aligned.m16n8k16.row.col.f32.bf16.bf16.f32 "
        "{%0,%1,%2,%3}, {%4,%5,%6,%7}, {%8,%9}, {%0,%1,%2,%3};"
        : "+f"(c[0]), "+f"(c[1]), "+f"(c[2]), "+f"(c[3])
        : "r"(a[0]), "r"(a[1]), "r"(a[2]), "r"(a[3]), "r"(b0), "r"(b1));
}
// x4 lane-split: lanes 0-15 -> BtH, lanes 16-31 -> BtL.
// Returns {b0,b1} = hi fragment, {b2,b3} = lo fragment of the same n-tile.
__device__ __forceinline__ void ldsm_x4(u32& b0, u32& b1, u32& b2, u32& b3, u32 addr) {
    asm volatile("ldmatrix.sync.aligned.m8n8.x4.shared.b16 {%0,%1,%2,%3}, [%4];"
                 : "=r"(b0), "=r"(b1), "=r"(b2), "=r"(b3) : "r"(addr));
}

// smem sizing helpers (host+device)
__host__ __device__ constexpr int ks_of(int K)    { return (3 * K * K + 15) / 16; }
__host__ __device__ constexpr int ks16_of(int K)  { return ks_of(K) * 16; }
__host__ __device__ constexpr int kpad_of(int K)  { return ks16_of(K) + 8; }   // odd 16B-stride
__host__ __device__ constexpr int slab_bytes(int K) { return NCH * kpad_of(K) * 2; }
__host__ __device__ constexpr int dyn_bytes(int K)  { return 2 * slab_bytes(K); }

// CTA = (nchunk, y, batch). 96 threads, 3 warps; each warp owns 2 m16 oc-tiles x 7 n-tiles.
// launch_bounds(96,7) caps regs at ~97 so occupancy doesn't collapse (R12 lesson).
template <int K>
__global__ __launch_bounds__(96, 7)
void conv_mma_kernel(const float* __restrict__ X, const float* __restrict__ Bv, int group)
{
    constexpr int P = (K - 1) / 2, KK = K * K, K3 = 3 * KK;
    constexpr int KS = ks_of(K);
    constexpr int KS16 = ks16_of(K);
    constexpr int KPAD = kpad_of(K);

    __shared__ __nv_bfloat16 rawH[3 * K * LW];
    __shared__ __nv_bfloat16 rawL[3 * K * LW];
    __shared__ int s_ofs[KS16];
    extern __shared__ __align__(16) char dynsm[];
    __nv_bfloat16* BtH = (__nv_bfloat16*)dynsm;
    __nv_bfloat16* BtL = (__nv_bfloat16*)(dynsm + slab_bytes(K));

    const int n0   = blockIdx.x * NCH;
    const int y    = blockIdx.y;
    const int b    = blockIdx.z;
    const int tid  = threadIdx.x;
    const int w    = tid >> 5;
    const int lane = tid & 31;

    // ---- k -> raw-offset table ----
    for (int k = tid; k < KS16; k += 96) {
        int o = -1;
        if (k < K3) {
            int ci = k / KK, rem = k - ci * KK;
            int dy = rem / K, dx = rem - dy * K;
            o = (ci * K + dy) * LW + dx;
        }
        s_ofs[k] = o;
    }

    // ---- stage raw rows (bf16 hi/lo), zero outside image ----
    const float* Xb = X + (size_t)b * 3 * NPIX;
    for (int i = tid; i < 3 * K * LW; i += 96) {
        int ci = i / (K * LW);
        int r  = i % (K * LW);
        int dy = r / LW, j = r % LW;
        int iy = y - P + dy, ix = n0 - P + j;
        float v = 0.0f;
        if (iy >= 0 && iy < IMG && ix >= 0 && ix < IMG)
            v = Xb[(ci * IMG + iy) * IMG + ix];
        __nv_bfloat16 h = __float2bfloat16(v);
        rawH[i] = h;
        rawL[i] = __float2bfloat16(v - __bfloat162float(h));
    }
    __syncthreads();

    // ---- build BOTH B slabs: thread = (n, k-octet); 2 aligned STS.128 per iter ----
    {
        const int NOCT = KS16 / 8;                     // k-octets per row
        for (int i = tid; i < NCH * NOCT; i += 96) {
            int n  = i / NOCT, k8 = (i - n * NOCT) * 8;
            unsigned short hv[8], lv[8];
            #pragma unroll
            for (int e = 0; e < 8; ++e) {
                int o = s_ofs[k8 + e];
                unsigned short h = 0, l = 0;
                if (o >= 0) {
                    h = __bfloat16_as_ushort(rawH[o + n]);
                    l = __bfloat16_as_ushort(rawL[o + n]);
                }
                hv[e] = h; lv[e] = l;
            }
            int d = n * KPAD + k8;                     // 16B-aligned (KPAD*2 and k8*2 are)
            *(uint4*)&BtH[d] = *(const uint4*)hv;
            *(uint4*)&BtL[d] = *(const uint4*)lv;
        }
    }
    __syncthreads();

    float acc[2][7][4];
    #pragma unroll
    for (int mt = 0; mt < 2; ++mt)
        #pragma unroll
        for (int nt = 0; nt < 7; ++nt)
            #pragma unroll
            for (int c = 0; c < 4; ++c) acc[mt][nt][c] = 0.0f;

    // a-frag base pointers (uint4 rows: [ks][lane] -> 16B)
    const uint4* afH0 = (const uint4*)&g_afrag[(((group * 2 + 0) * 6 + 2 * w + 0) * KSMAX) * 128];
    const uint4* afH1 = (const uint4*)&g_afrag[(((group * 2 + 0) * 6 + 2 * w + 1) * KSMAX) * 128];
    const uint4* afL0 = (const uint4*)&g_afrag[(((group * 2 + 1) * 6 + 2 * w + 0) * KSMAX) * 128];
    const uint4* afL1 = (const uint4*)&g_afrag[(((group * 2 + 1) * 6 + 2 * w + 1) * KSMAX) * 128];

    // ldsm.x4 lane-split addressing
    const u32 rowOff = (u32)((((lane & 7) * KPAD) + ((lane >> 3) & 1) * 8) * 2);
    const u32 lmBase = ((lane < 16) ? smem_u32(BtH) : smem_u32(BtL)) + rowOff;

    // ---- mainloop: per ks, 4 x LDG.128 (a-frags) + 7 x ldsm.x4 + 21 MMAs ----
    #pragma unroll
    for (int ks = 0; ks < KS; ++ks) {
        uint4 vh0 = afH0[ks * 32 + lane];
        uint4 vh1 = afH1[ks * 32 + lane];
        uint4 vl0 = afL0[ks * 32 + lane];
        uint4 vl1 = afL1[ks * 32 + lane];
        const u32* ah0 = (const u32*)&vh0;
        const u32* ah1 = (const u32*)&vh1;
        const u32* al0 = (const u32*)&vl0;
        const u32* al1 = (const u32*)&vl1;
        #pragma unroll
        for (int nt = 0; nt < 7; ++nt) {
            u32 b0, b1, c0, c1;
            ldsm_x4(b0, b1, c0, c1, lmBase + (u32)((nt * 8 * KPAD + ks * 16) * 2));
            mma16816(acc[0][nt], ah0, b0, b1);   // AhBh  (mt0)
            mma16816(acc[1][nt], ah1, b0, b1);   // AhBh  (mt1)
            mma16816(acc[0][nt], al0, b0, b1);   // AlBh  (mt0)
            mma16816(acc[1][nt], al1, b0, b1);   // AlBh  (mt1)
            mma16816(acc[0][nt], ah0, c0, c1);   // AhBl  (mt0)
            mma16816(acc[1][nt], ah1, c0, c1);   // AhBl  (mt1)
        }
    }

    // ---- epilogue: bias+relu+pool per m-tile, quad reduce, atomics ----
    const int r0 = lane >> 2;
    #pragma unroll
    for (int mt = 0; mt < 2; ++mt) {
        const int ocbase = (2 * w + mt) * 16;
        const float bias0 = Bv[ocbase + r0];
        const float bias1 = Bv[ocbase + r0 + 8];
        float cnt0 = 0, sum0 = 0, mx0 = 0, cnt1 = 0, sum1 = 0, mx1 = 0;
        #pragma unroll
        for (int nt = 0; nt < 7; ++nt) {
            #pragma unroll
            for (int c = 0; c < 2; ++c) {
                float v = acc[mt][nt][c] + bias0;
                float rl = fmaxf(v, 0.0f);
                cnt0 += (v > 0.0f) ? 1.0f : 0.0f; sum0 += rl; mx0 = fmaxf(mx0, rl);
            }
            #pragma unroll
            for (int c = 2; c < 4; ++c) {
                float v = acc[mt][nt][c] + bias1;
                float rl = fmaxf(v, 0.0f);
                cnt1 += (v > 0.0f) ? 1.0f : 0.0f; sum1 += rl; mx1 = fmaxf(mx1, rl);
            }
        }
        #pragma unroll
        for (int m = 1; m <= 2; m <<= 1) {
            cnt0 += __shfl_xor_sync(0xffffffffu, cnt0, m);
            sum0 += __shfl_xor_sync(0xffffffffu, sum0, m);
            mx0   = fmaxf(mx0, __shfl_xor_sync(0xffffffffu, mx0, m));
            cnt1 += __shfl_xor_sync(0xffffffffu, cnt1, m);
            sum1 += __shfl_xor_sync(0xffffffffu, sum1, m);
            mx1   = fmaxf(mx1, __shfl_xor_sync(0xffffffffu, mx1, m));
        }
        if ((lane & 3) == 0) {
            int base = (group * BATCH + b) * COUNT + ocbase;
            int i0 = base + r0, i1 = base + r0 + 8;
            atomicAdd(&g_cnt[i0], cnt0); atomicAdd(&g_sum[i0], sum0);
            atomicMax(&g_max[i0], __float_as_int(mx0));
            atomicAdd(&g_cnt[i1], cnt1); atomicAdd(&g_sum[i1], sum1);
            atomicMax(&g_max[i1], __float_as_int(mx1));
        }
    }
}

__global__ void finalize_kernel(float* __restrict__ out) {
    int i = blockIdx.x * blockDim.x + threadIdx.x;
    if (i >= ACC_N) return;
    int g = i / (BATCH * COUNT);
    int r = i % (BATCH * COUNT);
    int b = r / COUNT;
    int c = r % COUNT;
    float cnt = g_cnt[i];
    float sum = g_sum[i];
    float mx  = __int_as_float(g_max[i]);
    float ppv = cnt * (1.0f / (float)NPIX);
    float mpv = (cnt > 0.0f) ? (sum / cnt) : 0.0f;
    float* o = out + (size_t)b * (NGROUPS * 3 * COUNT) + g * (3 * COUNT);
    o[c]             = ppv;
    o[COUNT + c]     = mpv;
    o[2 * COUNT + c] = mx;
}

extern "C" void kernel_launch(void* const* d_in, const int* in_sizes, int n_in,
                              void* d_out, int out_size)
{
    const float* X  = (const float*)d_in[0];
    const float* w3 = (const float*)d_in[1];
    const float* b3 = (const float*)d_in[2];
    const float* w5 = (const float*)d_in[3];
    const float* b5 = (const float*)d_in[4];
    const float* w7 = (const float*)d_in[5];
    const float* b7 = (const float*)d_in[6];
    const float* w9 = (const float*)d_in[7];
    const float* b9 = (const float*)d_in[8];
    float* out = (float*)d_out;

    cudaFuncSetAttribute(conv_mma_kernel<3>, cudaFuncAttributeMaxDynamicSharedMemorySize, dyn_bytes(3));
    cudaFuncSetAttribute(conv_mma_kernel<5>, cudaFuncAttributeMaxDynamicSharedMemorySize, dyn_bytes(5));
    cudaFuncSetAttribute(conv_mma_kernel<7>, cudaFuncAttributeMaxDynamicSharedMemorySize, dyn_bytes(7));
    cudaFuncSetAttribute(conv_mma_kernel<9>, cudaFuncAttributeMaxDynamicSharedMemorySize, dyn_bytes(9));

    zero_acc_kernel<<<(ACC_N + 255) / 256, 256>>>();
    const int TOT = NGROUPS * 2 * 6 * KSMAX * 128;
    prepack_afrag_kernel<<<(TOT + 255) / 256, 256>>>(w3, w5, w7, w9);

    dim3 grid(IMG / NCH, IMG, BATCH);   // (4 chunks, 224 rows, 8 batches)
    conv_mma_kernel<3><<<grid, 96, dyn_bytes(3)>>>(X, b3, 0);
    conv_mma_kernel<5><<<grid, 96, dyn_bytes(5)>>>(X, b5, 1);
    conv_mma_kernel<7><<<grid, 96, dyn_bytes(7)>>>(X, b7, 2);
    conv_mma_kernel<9><<<grid, 96, dyn_bytes(9)>>>(X, b9, 3);

    finalize_kernel<<<(ACC_N + 255) / 256, 256>>>(out);
}

// round 16
// speedup vs baseline: 1.9172x; 1.7561x over previous
#include <cuda_runtime.h>
#include <cuda_bf16.h>

#define NGROUPS 4
#define COUNT   96
#define BATCH   8
#define IMG     224
#define NPIX    (IMG * IMG)
#define ACC_N   (NGROUPS * BATCH * COUNT)
#define KSMAX   16
#define NCH     56      // pixels per CTA chunk (7 n-tiles of 8)
#define LW      64      // staged raw row width

typedef unsigned int u32;

__device__ float g_cnt[ACC_N];
__device__ float g_sum[ACC_N];
__device__ int   g_max[ACC_N];
// A fragments prepacked in m16n8k16 register layout: [g][term][mtile][ks][lane][4] u32
__device__ u32 g_afrag[NGROUPS * 2 * 6 * KSMAX * 128];

__global__ void zero_acc_kernel() {
    int i = blockIdx.x * blockDim.x + threadIdx.x;
    if (i < ACC_N) { g_cnt[i] = 0.0f; g_sum[i] = 0.0f; g_max[i] = 0; }
}

__device__ __forceinline__ unsigned short bf16_bits(float v) {
    __nv_bfloat16 b = __float2bfloat16(v);
    return __bfloat16_as_ushort(b);
}

__global__ void prepack_afrag_kernel(const float* __restrict__ w3, const float* __restrict__ w5,
                                     const float* __restrict__ w7, const float* __restrict__ w9)
{
    int i = blockIdx.x * blockDim.x + threadIdx.x;
    const int TOT = NGROUPS * 2 * 6 * KSMAX * 128;
    if (i >= TOT) return;
    int r  = i & 3;
    int l  = (i >> 2) & 31;
    int ks = (i >> 7) & 15;
    int hi = i >> 11;              // [g][t][mt]
    int mt = hi % 6;
    int t  = (hi / 6) % 2;
    int g  = hi / 12;
    const int kss[4] = {3, 5, 7, 9};
    int K = kss[g], KK = K * K, K3 = 3 * KK;
    const float* W = (g == 0) ? w3 : (g == 1) ? w5 : (g == 2) ? w7 : w9;

    int row = (l >> 2) + (r & 1) * 8;
    int oc  = mt * 16 + row;
    int kb  = ks * 16 + (l & 3) * 2 + ((r >> 1) & 1) * 8;

    unsigned short us[2];
    #pragma unroll
    for (int e = 0; e < 2; ++e) {
        int k = kb + e;
        float v = 0.0f;
        if (k < K3) {
            int ci = k / KK, rem = k - ci * KK;
            int dy = rem / K, dx = rem - dy * K;
            v = W[((oc * 3 + ci) * K + dy) * K + dx];
        }
        float h = __bfloat162float(__float2bfloat16(v));
        us[e] = (t == 0) ? bf16_bits(v) : bf16_bits(v - h);
    }
    g_afrag[i] = (u32)us[0] | ((u32)us[1] << 16);
}

__device__ __forceinline__ u32 smem_u32(const void* p) {
    u32 a;
    asm("{ .reg .u64 t; cvta.to.shared.u64 t, %1; cvt.u32.u64 %0, t; }" : "=r"(a) : "l"(p));
    return a;
}
__device__ __forceinline__ void mma16816(float* c, const u32* a, u32 b0, u32 b1) {
    asm volatile(
        "mma.sync.aligned.m16n8k16.row.col.f32.bf16.bf16.f32 "
        "{%0,%1,%2,%3}, {%4,%5,%6,%7}, {%8,%9}, {%0,%1,%2,%3};"
        : "+f"(c[0]), "+f"(c[1]), "+f"(c[2]), "+f"(c[3])
        : "r"(a[0]), "r"(a[1]), "r"(a[2]), "r"(a[3]), "r"(b0), "r"(b1));
}
// x4 lane-split: lanes 0-15 -> BtH rows, lanes 16-31 -> BtL rows.
// Returns {b0,b1} = hi fragment, {b2,b3} = lo fragment of the same n-tile.
__device__ __forceinline__ void ldsm_x4(u32& b0, u32& b1, u32& b2, u32& b3, u32 addr) {
    asm volatile("ldmatrix.sync.aligned.m8n8.x4.shared.b16 {%0,%1,%2,%3}, [%4];"
                 : "=r"(b0), "=r"(b1), "=r"(b2), "=r"(b3) : "r"(addr));
}

// smem sizing helpers (host+device)
__host__ __device__ constexpr int ks_of(int K)    { return (3 * K * K + 15) / 16; }
__host__ __device__ constexpr int ks16_of(int K)  { return ks_of(K) * 16; }
__host__ __device__ constexpr int kpad_of(int K)  { return ks16_of(K) + 8; }   // odd 16B-stride
__host__ __device__ constexpr int slab_bytes(int K) { return NCH * kpad_of(K) * 2; }
__host__ __device__ constexpr int dyn_bytes(int K)  { return 2 * slab_bytes(K); }

// CTA = (nchunk, y, batch). 192 threads, 6 warps; each warp owns one m16 oc-tile.
template <int K>
__global__ __launch_bounds__(192)
void conv_mma_kernel(const float* __restrict__ X, const float* __restrict__ Bv, int group)
{
    constexpr int P = (K - 1) / 2, KK = K * K, K3 = 3 * KK;
    constexpr int KS = ks_of(K);
    constexpr int KS16 = ks16_of(K);
    constexpr int KPAD = kpad_of(K);
    constexpr int NOCT = KS16 / 8;

    __shared__ u32 rawHL[3 * K * LW];                  // packed (hi | lo<<16) per element
    __shared__ __align__(16) int s_ofs[KS16];
    extern __shared__ __align__(16) char dynsm[];
    __nv_bfloat16* BtH = (__nv_bfloat16*)dynsm;
    __nv_bfloat16* BtL = (__nv_bfloat16*)(dynsm + slab_bytes(K));

    const int n0   = blockIdx.x * NCH;
    const int y    = blockIdx.y;
    const int b    = blockIdx.z;
    const int tid  = threadIdx.x;
    const int w    = tid >> 5;
    const int lane = tid & 31;

    // ---- k -> raw-offset table ----
    for (int k = tid; k < KS16; k += 192) {
        int o = -1;
        if (k < K3) {
            int ci = k / KK, rem = k - ci * KK;
            int dy = rem / K, dx = rem - dy * K;
            o = (ci * K + dy) * LW + dx;
        }
        s_ofs[k] = o;
    }

    // ---- stage raw rows as packed u32 (bf16 hi | lo<<16), zero outside image ----
    const float* Xb = X + (size_t)b * 3 * NPIX;
    for (int i = tid; i < 3 * K * LW; i += 192) {
        int ci = i / (K * LW);
        int r  = i % (K * LW);
        int dy = r / LW, j = r % LW;
        int iy = y - P + dy, ix = n0 - P + j;
        float v = 0.0f;
        if (iy >= 0 && iy < IMG && ix >= 0 && ix < IMG)
            v = Xb[(ci * IMG + iy) * IMG + ix];
        unsigned short h = bf16_bits(v);
        unsigned short l = bf16_bits(v - __bfloat162float(__ushort_as_bfloat16(h)));
        rawHL[i] = (u32)h | ((u32)l << 16);
    }
    __syncthreads();

    // ---- octet build: per 8 k's: 2 LDS.128 (ofs) + 8 LDS.32 + 8 PRMT + 2 STS.128 ----
    for (int i = tid; i < NCH * NOCT; i += 192) {
        int n  = i / NOCT, k8 = (i - n * NOCT) * 8;
        int4 o0 = *(const int4*)&s_ofs[k8];
        int4 o1 = *(const int4*)&s_ofs[k8 + 4];
        u32 rw[8];
        rw[0] = (o0.x >= 0) ? rawHL[o0.x + n] : 0u;
        rw[1] = (o0.y >= 0) ? rawHL[o0.y + n] : 0u;
        rw[2] = (o0.z >= 0) ? rawHL[o0.z + n] : 0u;
        rw[3] = (o0.w >= 0) ? rawHL[o0.w + n] : 0u;
        rw[4] = (o1.x >= 0) ? rawHL[o1.x + n] : 0u;
        rw[5] = (o1.y >= 0) ? rawHL[o1.y + n] : 0u;
        rw[6] = (o1.z >= 0) ? rawHL[o1.z + n] : 0u;
        rw[7] = (o1.w >= 0) ? rawHL[o1.w + n] : 0u;
        uint4 hv, lv;
        hv.x = __byte_perm(rw[0], rw[1], 0x5410);  lv.x = __byte_perm(rw[0], rw[1], 0x7632);
        hv.y = __byte_perm(rw[2], rw[3], 0x5410);  lv.y = __byte_perm(rw[2], rw[3], 0x7632);
        hv.z = __byte_perm(rw[4], rw[5], 0x5410);  lv.z = __byte_perm(rw[4], rw[5], 0x7632);
        hv.w = __byte_perm(rw[6], rw[7], 0x5410);  lv.w = __byte_perm(rw[6], rw[7], 0x7632);
        int d = n * KPAD + k8;                     // 16B-aligned
        *(uint4*)&BtH[d] = hv;
        *(uint4*)&BtL[d] = lv;
    }
    __syncthreads();

    float acc[7][4];
    #pragma unroll
    for (int nt = 0; nt < 7; ++nt)
        #pragma unroll
        for (int c = 0; c < 4; ++c) acc[nt][c] = 0.0f;

    // a-frag base pointers (uint4 rows: [ks][lane] -> 16B)
    const uint4* afH = (const uint4*)&g_afrag[(((group * 2 + 0) * 6 + w) * KSMAX) * 128];
    const uint4* afL = (const uint4*)&g_afrag[(((group * 2 + 1) * 6 + w) * KSMAX) * 128];

    // ldsm.x4 lane-split addressing
    const u32 rowOff = (u32)((((lane & 7) * KPAD) + ((lane >> 3) & 1) * 8) * 2);
    const u32 lmBase = ((lane < 16) ? smem_u32(BtH) : smem_u32(BtL)) + rowOff;

    // ---- mainloop: per ks, 2 x LDG.128 (a-frags) + 7 x ldsm.x4 + 21 MMAs ----
    #pragma unroll
    for (int ks = 0; ks < KS; ++ks) {
        uint4 vh = afH[ks * 32 + lane];
        uint4 vl = afL[ks * 32 + lane];
        const u32* ah = (const u32*)&vh;
        const u32* al = (const u32*)&vl;
        #pragma unroll
        for (int nt = 0; nt < 7; ++nt) {
            u32 b0, b1, c0, c1;
            ldsm_x4(b0, b1, c0, c1, lmBase + (u32)((nt * 8 * KPAD + ks * 16) * 2));
            mma16816(acc[nt], ah, b0, b1);   // AhBh
            mma16816(acc[nt], al, b0, b1);   // AlBh
            mma16816(acc[nt], ah, c0, c1);   // AhBl
        }
    }

    // ---- epilogue: bias+relu+pool, quad reduce, atomics ----
    const int ocbase = w * 16;
    const int r0 = lane >> 2;
    const float bias0 = Bv[ocbase + r0];
    const float bias1 = Bv[ocbase + r0 + 8];
    float cnt0 = 0, sum0 = 0, mx0 = 0, cnt1 = 0, sum1 = 0, mx1 = 0;
    #pragma unroll
    for (int nt = 0; nt < 7; ++nt) {
        #pragma unroll
        for (int c = 0; c < 2; ++c) {
            float v = acc[nt][c] + bias0;
            float rl = fmaxf(v, 0.0f);
            cnt0 += (v > 0.0f) ? 1.0f : 0.0f; sum0 += rl; mx0 = fmaxf(mx0, rl);
        }
        #pragma unroll
        for (int c = 2; c < 4; ++c) {
            float v = acc[nt][c] + bias1;
            float rl = fmaxf(v, 0.0f);
            cnt1 += (v > 0.0f) ? 1.0f : 0.0f; sum1 += rl; mx1 = fmaxf(mx1, rl);
        }
    }
    #pragma unroll
    for (int m = 1; m <= 2; m <<= 1) {
        cnt0 += __shfl_xor_sync(0xffffffffu, cnt0, m);
        sum0 += __shfl_xor_sync(0xffffffffu, sum0, m);
        mx0   = fmaxf(mx0, __shfl_xor_sync(0xffffffffu, mx0, m));
        cnt1 += __shfl_xor_sync(0xffffffffu, cnt1, m);
        sum1 += __shfl_xor_sync(0xffffffffu, sum1, m);
        mx1   = fmaxf(mx1, __shfl_xor_sync(0xffffffffu, mx1, m));
    }
    if ((lane & 3) == 0) {
        int base = (group * BATCH + b) * COUNT + ocbase;
        int i0 = base + r0, i1 = base + r0 + 8;
        atomicAdd(&g_cnt[i0], cnt0); atomicAdd(&g_sum[i0], sum0);
        atomicMax(&g_max[i0], __float_as_int(mx0));
        atomicAdd(&g_cnt[i1], cnt1); atomicAdd(&g_sum[i1], sum1);
        atomicMax(&g_max[i1], __float_as_int(mx1));
    }
}

__global__ void finalize_kernel(float* __restrict__ out) {
    int i = blockIdx.x * blockDim.x + threadIdx.x;
    if (i >= ACC_N) return;
    int g = i / (BATCH * COUNT);
    int r = i % (BATCH * COUNT);
    int b = r / COUNT;
    int c = r % COUNT;
    float cnt = g_cnt[i];
    float sum = g_sum[i];
    float mx  = __int_as_float(g_max[i]);
    float ppv = cnt * (1.0f / (float)NPIX);
    float mpv = (cnt > 0.0f) ? (sum / cnt) : 0.0f;
    float* o = out + (size_t)b * (NGROUPS * 3 * COUNT) + g * (3 * COUNT);
    o[c]             = ppv;
    o[COUNT + c]     = mpv;
    o[2 * COUNT + c] = mx;
}

extern "C" void kernel_launch(void* const* d_in, const int* in_sizes, int n_in,
                              void* d_out, int out_size)
{
    const float* X  = (const float*)d_in[0];
    const float* w3 = (const float*)d_in[1];
    const float* b3 = (const float*)d_in[2];
    const float* w5 = (const float*)d_in[3];
    const float* b5 = (const float*)d_in[4];
    const float* w7 = (const float*)d_in[5];
    const float* b7 = (const float*)d_in[6];
    const float* w9 = (const float*)d_in[7];
    const float* b9 = (const float*)d_in[8];
    float* out = (float*)d_out;

    cudaFuncSetAttribute(conv_mma_kernel<3>, cudaFuncAttributeMaxDynamicSharedMemorySize, dyn_bytes(3));
    cudaFuncSetAttribute(conv_mma_kernel<5>, cudaFuncAttributeMaxDynamicSharedMemorySize, dyn_bytes(5));
    cudaFuncSetAttribute(conv_mma_kernel<7>, cudaFuncAttributeMaxDynamicSharedMemorySize, dyn_bytes(7));
    cudaFuncSetAttribute(conv_mma_kernel<9>, cudaFuncAttributeMaxDynamicSharedMemorySize, dyn_bytes(9));

    zero_acc_kernel<<<(ACC_N + 255) / 256, 256>>>();
    const int TOT = NGROUPS * 2 * 6 * KSMAX * 128;
    prepack_afrag_kernel<<<(TOT + 255) / 256, 256>>>(w3, w5, w7, w9);

    dim3 grid(IMG / NCH, IMG, BATCH);   // (4 chunks, 224 rows, 8 batches)
    conv_mma_kernel<3><<<grid, 192, dyn_bytes(3)>>>(X, b3, 0);
    conv_mma_kernel<5><<<grid, 192, dyn_bytes(5)>>>(X, b5, 1);
    conv_mma_kernel<7><<<grid, 192, dyn_bytes(7)>>>(X, b7, 2);
    conv_mma_kernel<9><<<grid, 192, dyn_bytes(9)>>>(X, b9, 3);

    finalize_kernel<<<(ACC_N + 255) / 256, 256>>>(out);
}